// round 1
// baseline (speedup 1.0000x reference)
#include <cuda_runtime.h>
#include <cstddef>

#define NE 2048     // n_embd
#define NH 16       // heads
#define HD 128      // head dim
#define SB 2048     // seq len
#define NB 2        // batch
#define MT 4096     // NB*SB rows

// Scratch (allocation-free rule: __device__ globals)
__device__ float g_q [MT * NE];   // [B,S,H,D]
__device__ float g_k [MT * HD];   // [B,S,D]
__device__ float g_v [MT * HD];   // [B,S,D]
__device__ float g_ao[MT * NE];   // attention output [B,S,H,D]

// ---------------------------------------------------------------------------
// GEMM: C[M,N] = A[M,K] @ W[N,K]^T + bias[N]
// 128x128x16 tiles, 256 threads, 8x8 micro-tile per thread (fp32 FFMA).
// M,N multiples of 128; K multiple of 16 (true for all calls here).
// ---------------------------------------------------------------------------
__global__ void __launch_bounds__(256)
gemm_bias(const float* __restrict__ A, const float* __restrict__ W,
          const float* __restrict__ bias, float* __restrict__ C,
          int M, int N, int K)
{
    __shared__ float As[16][132];   // A tile transposed: As[k][m]
    __shared__ float Bs[16][132];   // W tile transposed: Bs[k][n]

    const int tid = threadIdx.x;
    const int bm  = blockIdx.y * 128;
    const int bn  = blockIdx.x * 128;
    const int tr  = tid >> 4;          // 0..15, rows 8*tr..
    const int tc  = tid & 15;          // 0..15, cols 8*tc..
    const int lr  = tid >> 1;          // 0..127 loader row
    const int lk  = (tid & 1) * 8;     // 0 or 8 loader k-offset

    const float* Ag = A + (size_t)(bm + lr) * K + lk;
    const float* Wg = W + (size_t)(bn + lr) * K + lk;

    float acc[8][8];
    #pragma unroll
    for (int i = 0; i < 8; i++)
        #pragma unroll
        for (int j = 0; j < 8; j++) acc[i][j] = 0.f;

    for (int k0 = 0; k0 < K; k0 += 16) {
        float4 a0 = *(const float4*)(Ag + k0);
        float4 a1 = *(const float4*)(Ag + k0 + 4);
        float4 b0 = *(const float4*)(Wg + k0);
        float4 b1 = *(const float4*)(Wg + k0 + 4);
        __syncthreads();   // protect previous iteration's reads
        As[lk+0][lr] = a0.x; As[lk+1][lr] = a0.y; As[lk+2][lr] = a0.z; As[lk+3][lr] = a0.w;
        As[lk+4][lr] = a1.x; As[lk+5][lr] = a1.y; As[lk+6][lr] = a1.z; As[lk+7][lr] = a1.w;
        Bs[lk+0][lr] = b0.x; Bs[lk+1][lr] = b0.y; Bs[lk+2][lr] = b0.z; Bs[lk+3][lr] = b0.w;
        Bs[lk+4][lr] = b1.x; Bs[lk+5][lr] = b1.y; Bs[lk+6][lr] = b1.z; Bs[lk+7][lr] = b1.w;
        __syncthreads();
        #pragma unroll
        for (int k = 0; k < 16; k++) {
            float4 x0 = *(const float4*)&As[k][tr*8];
            float4 x1 = *(const float4*)&As[k][tr*8+4];
            float4 y0 = *(const float4*)&Bs[k][tc*8];
            float4 y1 = *(const float4*)&Bs[k][tc*8+4];
            float av[8] = {x0.x,x0.y,x0.z,x0.w,x1.x,x1.y,x1.z,x1.w};
            float bv[8] = {y0.x,y0.y,y0.z,y0.w,y1.x,y1.y,y1.z,y1.w};
            #pragma unroll
            for (int i = 0; i < 8; i++)
                #pragma unroll
                for (int j = 0; j < 8; j++)
                    acc[i][j] += av[i] * bv[j];
        }
    }

    float bv8[8];
    #pragma unroll
    for (int j = 0; j < 8; j++) bv8[j] = bias[bn + tc*8 + j];

    #pragma unroll
    for (int i = 0; i < 8; i++) {
        const int row = bm + tr*8 + i;
        float* Cp = C + (size_t)row * N + bn + tc*8;
        float4 o0 = make_float4(acc[i][0]+bv8[0], acc[i][1]+bv8[1],
                                acc[i][2]+bv8[2], acc[i][3]+bv8[3]);
        float4 o1 = make_float4(acc[i][4]+bv8[4], acc[i][5]+bv8[5],
                                acc[i][6]+bv8[6], acc[i][7]+bv8[7]);
        *(float4*)Cp       = o0;
        *(float4*)(Cp + 4) = o1;
    }
}

// ---------------------------------------------------------------------------
// MQA flash attention: per (b, h, q-tile of 64). Online softmax, causal.
// SMEM: Qt[128][64] (transposed, pre-scaled), KV buffer shared between
// Kt[128][64] (transposed) and Vs[64][132] (natural), Ps[64][65].
// 256 threads. O accumulator in registers (4 rows x 8 cols per thread).
// ---------------------------------------------------------------------------
#define ATTN_SMEM_FLOATS (8192 + 8448 + 4160 + 192)
#define ATTN_SMEM_BYTES  (ATTN_SMEM_FLOATS * 4)

__global__ void __launch_bounds__(256)
mqa_attn(const float* __restrict__ qp, const float* __restrict__ kp,
         const float* __restrict__ vp, float* __restrict__ ao)
{
    extern __shared__ float sm[];
    float* Qt     = sm;                    // [128][64]
    float* KV     = sm + 8192;             // Kt[128][64] OR Vs[64][132]
    float* Ps     = sm + 8192 + 8448;      // [64][65]
    float* row_m  = Ps + 4160;
    float* row_l  = row_m + 64;
    float* row_sc = row_l + 64;

    const int tid = threadIdx.x;
    const int qt = blockIdx.x, h = blockIdx.y, b = blockIdx.z;
    const int q0 = qt * 64;
    const float scale = 0.08838834764831845f;   // 1/sqrt(128)

    // loader indices: warp reads 16 rows x 32B contiguous chunks
    const int lp  = tid & 1;
    const int lr  = (tid >> 1) & 63;
    const int ldb = ((tid >> 7) << 3) + (lp << 2);   // {0,4,8,12}

    // ---- Q load: transpose + pre-scale ----
    {
        const float* qg = qp + ((size_t)(b * SB + q0 + lr) * NH + h) * HD;
        #pragma unroll
        for (int it = 0; it < 8; it++) {
            const int d = ldb + it * 16;
            float4 t = *(const float4*)(qg + d);
            Qt[(d+0)*64 + lr] = t.x * scale;
            Qt[(d+1)*64 + lr] = t.y * scale;
            Qt[(d+2)*64 + lr] = t.z * scale;
            Qt[(d+3)*64 + lr] = t.w * scale;
        }
    }
    if (tid < 64) { row_m[tid] = -1e30f; row_l[tid] = 0.f; }

    float o[4][8];
    #pragma unroll
    for (int i = 0; i < 4; i++)
        #pragma unroll
        for (int j = 0; j < 8; j++) o[i][j] = 0.f;

    const int tq = tid & 15;    // S rows group (4*tq..)
    const int tk = tid >> 4;    // S cols group (4*tk..)
    const int ro = tid >> 4;    // O rows group (4*ro..)
    const int co = tid & 15;    // O cols group (8*co..)
    const int sr = tid >> 2;    // softmax row
    const int sb = tid & 3;     // softmax sub

    __syncthreads();

    for (int jt = 0; jt <= qt; jt++) {
        const int kv0 = jt * 64;

        // ---- K load: transpose into KV ----
        {
            const float* kg = kp + (size_t)(b * SB + kv0 + lr) * HD;
            #pragma unroll
            for (int it = 0; it < 8; it++) {
                const int d = ldb + it * 16;
                float4 t = *(const float4*)(kg + d);
                KV[(d+0)*64 + lr] = t.x;
                KV[(d+1)*64 + lr] = t.y;
                KV[(d+2)*64 + lr] = t.z;
                KV[(d+3)*64 + lr] = t.w;
            }
        }
        __syncthreads();

        // ---- S = Q K^T (4x4 per thread) ----
        float s[4][4];
        #pragma unroll
        for (int i = 0; i < 4; i++)
            #pragma unroll
            for (int j = 0; j < 4; j++) s[i][j] = 0.f;

        #pragma unroll 4
        for (int d = 0; d < 128; d++) {
            float4 qv = *(const float4*)&Qt[d*64 + 4*tq];
            float4 kv = *(const float4*)&KV[d*64 + 4*tk];
            float qa[4] = {qv.x, qv.y, qv.z, qv.w};
            float ka[4] = {kv.x, kv.y, kv.z, kv.w};
            #pragma unroll
            for (int i = 0; i < 4; i++)
                #pragma unroll
                for (int j = 0; j < 4; j++)
                    s[i][j] += qa[i] * ka[j];
        }

        if (jt == qt) {
            #pragma unroll
            for (int i = 0; i < 4; i++)
                #pragma unroll
                for (int j = 0; j < 4; j++)
                    if (4*tk + j > 4*tq + i) s[i][j] = -1e30f;
        }
        #pragma unroll
        for (int i = 0; i < 4; i++)
            #pragma unroll
            for (int j = 0; j < 4; j++)
                Ps[(4*tq+i)*65 + 4*tk+j] = s[i][j];
        __syncthreads();   // Ps ready; Kt no longer needed

        // ---- online softmax (4 threads per row) ----
        {
            float* prow = Ps + sr*65 + sb*16;
            float mx = -1e30f;
            #pragma unroll
            for (int c = 0; c < 16; c++) mx = fmaxf(mx, prow[c]);
            mx = fmaxf(mx, __shfl_xor_sync(0xffffffffu, mx, 1));
            mx = fmaxf(mx, __shfl_xor_sync(0xffffffffu, mx, 2));
            const float m_old = row_m[sr];
            const float m_new = fmaxf(m_old, mx);
            const float scl   = __expf(m_old - m_new);
            float ls = 0.f;
            #pragma unroll
            for (int c = 0; c < 16; c++) {
                float p = __expf(prow[c] - m_new);
                prow[c] = p;
                ls += p;
            }
            ls += __shfl_xor_sync(0xffffffffu, ls, 1);
            ls += __shfl_xor_sync(0xffffffffu, ls, 2);
            if (sb == 0) {
                row_m[sr]  = m_new;
                row_l[sr]  = row_l[sr] * scl + ls;
                row_sc[sr] = scl;
            }
        }

        // ---- V load into KV (natural [64][132]) ----
        {
            const float* vg = vp + (size_t)(b * SB + kv0) * HD;
            #pragma unroll
            for (int it = 0; it < 8; it++) {
                const int f = tid * 4 + it * 1024;
                const int r = f >> 7, c = f & 127;
                *(float4*)&KV[r*132 + c] = *(const float4*)(vg + f);
            }
        }
        __syncthreads();   // V + exponentiated Ps + row_sc all ready

        // ---- O = O*scale + P V ----
        float rs[4];
        #pragma unroll
        for (int i = 0; i < 4; i++) rs[i] = row_sc[4*ro + i];
        #pragma unroll
        for (int i = 0; i < 4; i++)
            #pragma unroll
            for (int j = 0; j < 8; j++) o[i][j] *= rs[i];

        #pragma unroll 2
        for (int j = 0; j < 64; j++) {
            float4 v0 = *(const float4*)&KV[j*132 + 8*co];
            float4 v1 = *(const float4*)&KV[j*132 + 8*co + 4];
            #pragma unroll
            for (int i = 0; i < 4; i++) {
                const float p = Ps[(4*ro+i)*65 + j];
                o[i][0] += p * v0.x;  o[i][1] += p * v0.y;
                o[i][2] += p * v0.z;  o[i][3] += p * v0.w;
                o[i][4] += p * v1.x;  o[i][5] += p * v1.y;
                o[i][6] += p * v1.z;  o[i][7] += p * v1.w;
            }
        }
        __syncthreads();   // done with KV/Ps before next tile overwrites
    }

    // ---- finalize: divide by l, write [B,S,H,D] ----
    #pragma unroll
    for (int i = 0; i < 4; i++) {
        const float inv = 1.f / row_l[4*ro + i];
        const int row = q0 + 4*ro + i;
        float* og = ao + ((size_t)(b * SB + row) * NH + h) * HD + 8*co;
        float4 w0 = make_float4(o[i][0]*inv, o[i][1]*inv, o[i][2]*inv, o[i][3]*inv);
        float4 w1 = make_float4(o[i][4]*inv, o[i][5]*inv, o[i][6]*inv, o[i][7]*inv);
        *(float4*)og       = w0;
        *(float4*)(og + 4) = w1;
    }
}

// ---------------------------------------------------------------------------
extern "C" void kernel_launch(void* const* d_in, const int* in_sizes, int n_in,
                              void* d_out, int out_size)
{
    const float* x  = (const float*)d_in[0];
    const float* Wq = (const float*)d_in[1];
    const float* bq = (const float*)d_in[2];
    const float* Wk = (const float*)d_in[3];
    const float* bk = (const float*)d_in[4];
    const float* Wv = (const float*)d_in[5];
    const float* bv = (const float*)d_in[6];
    const float* Wo = (const float*)d_in[7];
    const float* bo = (const float*)d_in[8];
    float* out = (float*)d_out;

    float *qp, *kp, *vp, *aop;
    cudaGetSymbolAddress((void**)&qp,  g_q);
    cudaGetSymbolAddress((void**)&kp,  g_k);
    cudaGetSymbolAddress((void**)&vp,  g_v);
    cudaGetSymbolAddress((void**)&aop, g_ao);

    cudaFuncSetAttribute(mqa_attn, cudaFuncAttributeMaxDynamicSharedMemorySize,
                         ATTN_SMEM_BYTES);

    dim3 blk(256);
    // Q projection: [4096,2048] = x @ Wq^T + bq
    gemm_bias<<<dim3(NE/128, MT/128), blk>>>(x, Wq, bq, qp, MT, NE, NE);
    // K projection: [4096,128]
    gemm_bias<<<dim3(HD/128, MT/128), blk>>>(x, Wk, bk, kp, MT, HD, NE);
    // V projection: [4096,128]
    gemm_bias<<<dim3(HD/128, MT/128), blk>>>(x, Wv, bv, vp, MT, HD, NE);
    // Attention: grid (q-tiles, heads, batch)
    mqa_attn<<<dim3(SB/64, NH, NB), blk, ATTN_SMEM_BYTES>>>(qp, kp, vp, aop);
    // Output projection: [4096,2048] = ao @ Wo^T + bo
    gemm_bias<<<dim3(NE/128, MT/128), blk>>>(aop, Wo, bo, out, MT, NE, NE);
}

// round 3
// speedup vs baseline: 2.1740x; 2.1740x over previous
#include <cuda_runtime.h>
#include <cuda_fp16.h>
#include <cstdint>
#include <cstddef>

#define NE 2048
#define NH 16
#define HD 128
#define SB 2048
#define NB 2
#define MT 4096   // NB*SB

// ---------------- scratch (__device__ globals; no allocs) ------------------
__device__ float  g_q  [MT * NE];        // Q fp32 [B,S,H*D]
__device__ float  g_kv [MT * 256];       // fused K|V fp32, row stride 256
__device__ __half g_xh [MT * NE];        // fp16 activations
__device__ __half g_wqh[NE * NE];
__device__ __half g_wkvh[256 * NE];      // Wk rows 0-127, Wv rows 128-255
__device__ __half g_woh[NE * NE];
__device__ float  g_bkv[256];            // bk|bv concat
__device__ __half g_aoh[MT * NE];        // attention out fp16

// ---------------- PTX helpers (sm_80-safe; no 'a' features) ----------------
#define CP16(sa, g)  asm volatile("cp.async.cg.shared.global [%0], [%1], 16;" :: "r"(sa), "l"(g))
#define CP_COMMIT()  asm volatile("cp.async.commit_group;" ::: "memory")
#define CP_WAIT1()   asm volatile("cp.async.wait_group 1;" ::: "memory")

#define LDSM_X4(r0,r1,r2,r3, addr) \
    asm volatile("ldmatrix.sync.aligned.m8n8.x4.shared.b16 {%0,%1,%2,%3}, [%4];" \
        : "=r"(r0),"=r"(r1),"=r"(r2),"=r"(r3) : "r"(addr))
#define LDSM_X2(r0,r1, addr) \
    asm volatile("ldmatrix.sync.aligned.m8n8.x2.shared.b16 {%0,%1}, [%2];" \
        : "=r"(r0),"=r"(r1) : "r"(addr))
#define MMA16816(c0,c1,c2,c3, a0,a1,a2,a3, b0,b1) \
    asm volatile("mma.sync.aligned.m16n8k16.row.col.f32.f16.f16.f32 " \
        "{%0,%1,%2,%3}, {%4,%5,%6,%7}, {%8,%9}, {%0,%1,%2,%3};" \
        : "+f"(c0),"+f"(c1),"+f"(c2),"+f"(c3) \
        : "r"(a0),"r"(a1),"r"(a2),"r"(a3),"r"(b0),"r"(b1))

__device__ __forceinline__ uint32_t smem_u32(const void* p) {
    return (uint32_t)__cvta_generic_to_shared(p);
}

// ---------------- fp32 -> fp16 convert -------------------------------------
__global__ void __launch_bounds__(256)
f32_to_f16(const float* __restrict__ in, __half* __restrict__ out, int n)
{
    int i = (blockIdx.x * 256 + threadIdx.x) * 4;
    if (i < n) {
        float4 v = *(const float4*)(in + i);
        __half2* o = (__half2*)(out + i);
        o[0] = __floats2half2_rn(v.x, v.y);
        o[1] = __floats2half2_rn(v.z, v.w);
    }
}

__global__ void concat_bias(const float* __restrict__ bk,
                            const float* __restrict__ bv,
                            float* __restrict__ out)
{
    int t = threadIdx.x;
    out[t] = (t < 128) ? bk[t] : bv[t - 128];
}

// ---------------------------------------------------------------------------
// HMMA GEMM: C[M,N] = A[M,K](fp16 K-major) @ B[N,K](fp16 K-major)^T + bias
// 128x128 CTA tile, BK=32, 3-stage cp.async pipeline, 256 threads (8 warps),
// warp tile 64x32, mma.sync.m16n8k16 fp16->fp32.
// M,N multiples of 128; K multiple of 32.
// ---------------------------------------------------------------------------
#define PAD 40                              // halves per smem row (32 + 8 pad)
#define STG (128 * PAD)                     // halves per tile per stage
#define AOFF(st) ((st) * STG * 2)           // bytes
#define BOFF(st) (3 * STG * 2 + (st) * STG * 2)
#define GEMM_SMEM (6 * STG * 2)             // 61440 B

__global__ void __launch_bounds__(256)
gemm_hmma(const __half* __restrict__ A, const __half* __restrict__ B,
          const float* __restrict__ bias, float* __restrict__ C,
          int M, int N, int K)
{
    extern __shared__ __half sh[];
    const uint32_t smb = smem_u32(sh);

    const int tid  = threadIdx.x;
    const int wid  = tid >> 5;
    const int lane = tid & 31;
    const int bm = blockIdx.y * 128;
    const int bn = blockIdx.x * 128;
    const int m0 = (wid >> 2) * 64;     // warp row base within tile
    const int n0 = (wid & 3) * 32;      // warp col base within tile

    const int lrow = tid >> 2;          // 0..63 loader row (x2 passes -> 128)
    const int lch  = tid & 3;           // 16B chunk within 32-half row

    float c[4][4][4];
    #pragma unroll
    for (int mt = 0; mt < 4; mt++)
        #pragma unroll
        for (int nt = 0; nt < 4; nt++)
            #pragma unroll
            for (int r = 0; r < 4; r++) c[mt][nt][r] = 0.f;

    const __half* Ab = A + (size_t)bm * K;
    const __half* Bb = B + (size_t)bn * K;
    const int nk = K / 32;

    // ---- stage loader ----
    auto load_stage = [&](int st, int k0) {
        #pragma unroll
        for (int r = 0; r < 2; r++) {
            const int row = lrow + r * 64;
            const uint32_t so = (uint32_t)(row * PAD + lch * 8) * 2;
            CP16(smb + AOFF(st) + so, Ab + (size_t)row * K + k0 + lch * 8);
            CP16(smb + BOFF(st) + so, Bb + (size_t)row * K + k0 + lch * 8);
        }
    };

    load_stage(0, 0);  CP_COMMIT();
    load_stage(1, 32); CP_COMMIT();

    // ldmatrix lane addressing (constant per thread)
    const int a_r = lane & 15, a_c = (lane >> 4) * 8;
    const int b_r = lane & 7,  b_c = ((lane >> 3) & 1) * 8;

    for (int i = 0; i < nk; i++) {
        CP_WAIT1();
        __syncthreads();
        if (i + 2 < nk) load_stage((i + 2) % 3, (i + 2) * 32);
        CP_COMMIT();

        const int st = i % 3;
        #pragma unroll
        for (int ks = 0; ks < 2; ks++) {
            uint32_t a[4][4], b[4][2];
            #pragma unroll
            for (int mt = 0; mt < 4; mt++) {
                const uint32_t addr = smb + AOFF(st) +
                    (uint32_t)((m0 + mt * 16 + a_r) * PAD + ks * 16 + a_c) * 2;
                LDSM_X4(a[mt][0], a[mt][1], a[mt][2], a[mt][3], addr);
            }
            #pragma unroll
            for (int nt = 0; nt < 4; nt++) {
                const uint32_t addr = smb + BOFF(st) +
                    (uint32_t)((n0 + nt * 8 + b_r) * PAD + ks * 16 + b_c) * 2;
                LDSM_X2(b[nt][0], b[nt][1], addr);
            }
            #pragma unroll
            for (int mt = 0; mt < 4; mt++)
                #pragma unroll
                for (int nt = 0; nt < 4; nt++)
                    MMA16816(c[mt][nt][0], c[mt][nt][1], c[mt][nt][2], c[mt][nt][3],
                             a[mt][0], a[mt][1], a[mt][2], a[mt][3],
                             b[nt][0], b[nt][1]);
        }
        __syncthreads();
    }

    // ---- epilogue: add bias, write fp32 ----
    const int tr  = lane >> 2;
    const int tc2 = (lane & 3) * 2;
    #pragma unroll
    for (int mt = 0; mt < 4; mt++) {
        const int r0 = bm + m0 + mt * 16 + tr;
        #pragma unroll
        for (int nt = 0; nt < 4; nt++) {
            const int cc = bn + n0 + nt * 8 + tc2;
            const float bx = bias[cc], by = bias[cc + 1];
            float2 o0 = make_float2(c[mt][nt][0] + bx, c[mt][nt][1] + by);
            float2 o1 = make_float2(c[mt][nt][2] + bx, c[mt][nt][3] + by);
            *(float2*)&C[(size_t)r0 * N + cc]       = o0;
            *(float2*)&C[(size_t)(r0 + 8) * N + cc] = o1;
        }
    }
}

// ---------------------------------------------------------------------------
// MQA flash attention (fp32), K/V from fused buffer (row stride 256),
// output fp16 [B,S,H*D].
// ---------------------------------------------------------------------------
#define ATTN_SMEM_FLOATS (8192 + 8448 + 4160 + 192)
#define ATTN_SMEM_BYTES  (ATTN_SMEM_FLOATS * 4)

__global__ void __launch_bounds__(256)
mqa_attn(const float* __restrict__ qp, const float* __restrict__ kvp,
         __half* __restrict__ ao)
{
    extern __shared__ float smf[];
    float* Qt     = smf;
    float* KV     = smf + 8192;
    float* Ps     = smf + 8192 + 8448;
    float* row_m  = Ps + 4160;
    float* row_l  = row_m + 64;
    float* row_sc = row_l + 64;

    const int tid = threadIdx.x;
    const int qt = blockIdx.x, h = blockIdx.y, b = blockIdx.z;
    const int q0 = qt * 64;
    const float scale = 0.08838834764831845f;

    const int lp  = tid & 1;
    const int lr  = (tid >> 1) & 63;
    const int ldb = ((tid >> 7) << 3) + (lp << 2);

    {
        const float* qg = qp + ((size_t)(b * SB + q0 + lr) * NH + h) * HD;
        #pragma unroll
        for (int it = 0; it < 8; it++) {
            const int d = ldb + it * 16;
            float4 t = *(const float4*)(qg + d);
            Qt[(d+0)*64 + lr] = t.x * scale;
            Qt[(d+1)*64 + lr] = t.y * scale;
            Qt[(d+2)*64 + lr] = t.z * scale;
            Qt[(d+3)*64 + lr] = t.w * scale;
        }
    }
    if (tid < 64) { row_m[tid] = -1e30f; row_l[tid] = 0.f; }

    float o[4][8];
    #pragma unroll
    for (int i = 0; i < 4; i++)
        #pragma unroll
        for (int j = 0; j < 8; j++) o[i][j] = 0.f;

    const int tq = tid & 15;
    const int tk = tid >> 4;
    const int ro = tid >> 4;
    const int co = tid & 15;
    const int sr = tid >> 2;
    const int sb = tid & 3;

    __syncthreads();

    for (int jt = 0; jt <= qt; jt++) {
        const int kv0 = jt * 64;
        {
            const float* kg = kvp + (size_t)(b * SB + kv0 + lr) * 256;
            #pragma unroll
            for (int it = 0; it < 8; it++) {
                const int d = ldb + it * 16;
                float4 t = *(const float4*)(kg + d);
                KV[(d+0)*64 + lr] = t.x;
                KV[(d+1)*64 + lr] = t.y;
                KV[(d+2)*64 + lr] = t.z;
                KV[(d+3)*64 + lr] = t.w;
            }
        }
        __syncthreads();

        float s[4][4];
        #pragma unroll
        for (int i = 0; i < 4; i++)
            #pragma unroll
            for (int j = 0; j < 4; j++) s[i][j] = 0.f;

        #pragma unroll 4
        for (int d = 0; d < 128; d++) {
            float4 qv = *(const float4*)&Qt[d*64 + 4*tq];
            float4 kv = *(const float4*)&KV[d*64 + 4*tk];
            float qa[4] = {qv.x, qv.y, qv.z, qv.w};
            float ka[4] = {kv.x, kv.y, kv.z, kv.w};
            #pragma unroll
            for (int i = 0; i < 4; i++)
                #pragma unroll
                for (int j = 0; j < 4; j++)
                    s[i][j] += qa[i] * ka[j];
        }

        if (jt == qt) {
            #pragma unroll
            for (int i = 0; i < 4; i++)
                #pragma unroll
                for (int j = 0; j < 4; j++)
                    if (4*tk + j > 4*tq + i) s[i][j] = -1e30f;
        }
        #pragma unroll
        for (int i = 0; i < 4; i++)
            #pragma unroll
            for (int j = 0; j < 4; j++)
                Ps[(4*tq+i)*65 + 4*tk+j] = s[i][j];
        __syncthreads();

        {
            float* prow = Ps + sr*65 + sb*16;
            float mx = -1e30f;
            #pragma unroll
            for (int cc = 0; cc < 16; cc++) mx = fmaxf(mx, prow[cc]);
            mx = fmaxf(mx, __shfl_xor_sync(0xffffffffu, mx, 1));
            mx = fmaxf(mx, __shfl_xor_sync(0xffffffffu, mx, 2));
            const float m_old = row_m[sr];
            const float m_new = fmaxf(m_old, mx);
            const float scl   = __expf(m_old - m_new);
            float ls = 0.f;
            #pragma unroll
            for (int cc = 0; cc < 16; cc++) {
                float p = __expf(prow[cc] - m_new);
                prow[cc] = p;
                ls += p;
            }
            ls += __shfl_xor_sync(0xffffffffu, ls, 1);
            ls += __shfl_xor_sync(0xffffffffu, ls, 2);
            if (sb == 0) {
                row_m[sr]  = m_new;
                row_l[sr]  = row_l[sr] * scl + ls;
                row_sc[sr] = scl;
            }
        }

        {
            const float* vg = kvp + (size_t)(b * SB + kv0) * 256 + 128;
            #pragma unroll
            for (int it = 0; it < 8; it++) {
                const int f = tid * 4 + it * 1024;
                const int r = f >> 7, cc = f & 127;
                *(float4*)&KV[r*132 + cc] = *(const float4*)(vg + r * 256 + cc);
            }
        }
        __syncthreads();

        float rs[4];
        #pragma unroll
        for (int i = 0; i < 4; i++) rs[i] = row_sc[4*ro + i];
        #pragma unroll
        for (int i = 0; i < 4; i++)
            #pragma unroll
            for (int j = 0; j < 8; j++) o[i][j] *= rs[i];

        #pragma unroll 2
        for (int j = 0; j < 64; j++) {
            float4 v0 = *(const float4*)&KV[j*132 + 8*co];
            float4 v1 = *(const float4*)&KV[j*132 + 8*co + 4];
            #pragma unroll
            for (int i = 0; i < 4; i++) {
                const float p = Ps[(4*ro+i)*65 + j];
                o[i][0] += p * v0.x;  o[i][1] += p * v0.y;
                o[i][2] += p * v0.z;  o[i][3] += p * v0.w;
                o[i][4] += p * v1.x;  o[i][5] += p * v1.y;
                o[i][6] += p * v1.z;  o[i][7] += p * v1.w;
            }
        }
        __syncthreads();
    }

    #pragma unroll
    for (int i = 0; i < 4; i++) {
        const float inv = 1.f / row_l[4*ro + i];
        const int row = q0 + 4*ro + i;
        __half2* og = (__half2*)(ao + ((size_t)(b * SB + row) * NH + h) * HD + 8*co);
        og[0] = __floats2half2_rn(o[i][0]*inv, o[i][1]*inv);
        og[1] = __floats2half2_rn(o[i][2]*inv, o[i][3]*inv);
        og[2] = __floats2half2_rn(o[i][4]*inv, o[i][5]*inv);
        og[3] = __floats2half2_rn(o[i][6]*inv, o[i][7]*inv);
    }
}

// ---------------------------------------------------------------------------
extern "C" void kernel_launch(void* const* d_in, const int* in_sizes, int n_in,
                              void* d_out, int out_size)
{
    const float* x  = (const float*)d_in[0];
    const float* Wq = (const float*)d_in[1];
    const float* bq = (const float*)d_in[2];
    const float* Wk = (const float*)d_in[3];
    const float* bk = (const float*)d_in[4];
    const float* Wv = (const float*)d_in[5];
    const float* bv = (const float*)d_in[6];
    const float* Wo = (const float*)d_in[7];
    const float* bo = (const float*)d_in[8];
    float* out = (float*)d_out;

    float *qp, *kvp, *bkv;
    __half *xh, *wqh, *wkvh, *woh, *aoh;
    cudaGetSymbolAddress((void**)&qp,   g_q);
    cudaGetSymbolAddress((void**)&kvp,  g_kv);
    cudaGetSymbolAddress((void**)&bkv,  g_bkv);
    cudaGetSymbolAddress((void**)&xh,   g_xh);
    cudaGetSymbolAddress((void**)&wqh,  g_wqh);
    cudaGetSymbolAddress((void**)&wkvh, g_wkvh);
    cudaGetSymbolAddress((void**)&woh,  g_woh);
    cudaGetSymbolAddress((void**)&aoh,  g_aoh);

    cudaFuncSetAttribute(gemm_hmma, cudaFuncAttributeMaxDynamicSharedMemorySize, GEMM_SMEM);
    cudaFuncSetAttribute(mqa_attn,  cudaFuncAttributeMaxDynamicSharedMemorySize, ATTN_SMEM_BYTES);

    dim3 blk(256);

    // fp16 conversions (+ K|V weight fusion, bias concat)
    f32_to_f16<<<(MT * NE) / 1024, blk>>>(x,  xh,  MT * NE);
    f32_to_f16<<<(NE * NE) / 1024, blk>>>(Wq, wqh, NE * NE);
    f32_to_f16<<<(HD * NE) / 1024, blk>>>(Wk, wkvh,            HD * NE);
    f32_to_f16<<<(HD * NE) / 1024, blk>>>(Wv, wkvh + HD * NE,  HD * NE);
    f32_to_f16<<<(NE * NE) / 1024, blk>>>(Wo, woh, NE * NE);
    concat_bias<<<1, 256>>>(bk, bv, bkv);

    // projections on HMMA tensor cores
    gemm_hmma<<<dim3(NE / 128, MT / 128), blk, GEMM_SMEM>>>(xh, wqh,  bq,  qp,  MT, NE,  NE);
    gemm_hmma<<<dim3(256 / 128, MT / 128), blk, GEMM_SMEM>>>(xh, wkvh, bkv, kvp, MT, 256, NE);

    // attention (fp32 math, fp16 output)
    mqa_attn<<<dim3(SB / 64, NH, NB), blk, ATTN_SMEM_BYTES>>>(qp, kvp, aoh);

    // output projection
    gemm_hmma<<<dim3(NE / 128, MT / 128), blk, GEMM_SMEM>>>(aoh, woh, bo, out, MT, NE, NE);
}

// round 4
// speedup vs baseline: 7.4489x; 3.4264x over previous
#include <cuda_runtime.h>
#include <cuda_fp16.h>
#include <cstdint>
#include <cstddef>

#define NE 2048
#define NH 16
#define HD 128
#define SB 2048
#define NB 2
#define MT 4096   // NB*SB

// ---------------- scratch (__device__ globals; no allocs) ------------------
__device__ __half g_xh  [MT * NE];       // fp16 activations
__device__ __half g_qh  [MT * NE];       // fp16 Q (pre-scaled), [B,S,H*D]
__device__ __half g_kvh [MT * 256];      // fp16 fused K|V, row stride 256
__device__ __half g_aoh [MT * NE];       // attention out fp16
__device__ __half g_wqh [NE * NE];       // Wq * scale
__device__ __half g_wkvh[256 * NE];      // Wk rows 0-127, Wv rows 128-255
__device__ __half g_woh [NE * NE];
__device__ float  g_bqs [NE];            // bq * scale
__device__ float  g_bkv [256];           // bk|bv concat

// ---------------- PTX helpers (sm_80-safe; no 'a' features) ----------------
#define CP16(sa, g)  asm volatile("cp.async.cg.shared.global [%0], [%1], 16;" :: "r"(sa), "l"(g))
#define CP_COMMIT()  asm volatile("cp.async.commit_group;" ::: "memory")
#define CP_WAIT1()   asm volatile("cp.async.wait_group 1;" ::: "memory")
#define CP_WAIT0()   asm volatile("cp.async.wait_group 0;" ::: "memory")

#define LDSM_X4(r0,r1,r2,r3, addr) \
    asm volatile("ldmatrix.sync.aligned.m8n8.x4.shared.b16 {%0,%1,%2,%3}, [%4];" \
        : "=r"(r0),"=r"(r1),"=r"(r2),"=r"(r3) : "r"(addr))
#define LDSM_X4T(r0,r1,r2,r3, addr) \
    asm volatile("ldmatrix.sync.aligned.m8n8.x4.trans.shared.b16 {%0,%1,%2,%3}, [%4];" \
        : "=r"(r0),"=r"(r1),"=r"(r2),"=r"(r3) : "r"(addr))
#define LDSM_X2(r0,r1, addr) \
    asm volatile("ldmatrix.sync.aligned.m8n8.x2.shared.b16 {%0,%1}, [%2];" \
        : "=r"(r0),"=r"(r1) : "r"(addr))
#define MMA16816(c0,c1,c2,c3, a0,a1,a2,a3, b0,b1) \
    asm volatile("mma.sync.aligned.m16n8k16.row.col.f32.f16.f16.f32 " \
        "{%0,%1,%2,%3}, {%4,%5,%6,%7}, {%8,%9}, {%0,%1,%2,%3};" \
        : "+f"(c0),"+f"(c1),"+f"(c2),"+f"(c3) \
        : "r"(a0),"r"(a1),"r"(a2),"r"(a3),"r"(b0),"r"(b1))

__device__ __forceinline__ uint32_t smem_u32(const void* p) {
    return (uint32_t)__cvta_generic_to_shared(p);
}
__device__ __forceinline__ uint32_t pack_h2(float a, float b) {
    __half2 h = __floats2half2_rn(a, b);
    return *(uint32_t*)&h;
}

// ---------------- small conversion kernels ----------------------------------
__global__ void __launch_bounds__(256)
f32_to_f16(const float* __restrict__ in, __half* __restrict__ out, int n)
{
    int i = (blockIdx.x * 256 + threadIdx.x) * 4;
    if (i < n) {
        float4 v = *(const float4*)(in + i);
        __half2* o = (__half2*)(out + i);
        o[0] = __floats2half2_rn(v.x, v.y);
        o[1] = __floats2half2_rn(v.z, v.w);
    }
}
__global__ void __launch_bounds__(256)
f32_to_f16_s(const float* __restrict__ in, __half* __restrict__ out, int n, float s)
{
    int i = (blockIdx.x * 256 + threadIdx.x) * 4;
    if (i < n) {
        float4 v = *(const float4*)(in + i);
        __half2* o = (__half2*)(out + i);
        o[0] = __floats2half2_rn(v.x * s, v.y * s);
        o[1] = __floats2half2_rn(v.z * s, v.w * s);
    }
}
__global__ void scale_f32(const float* __restrict__ in, float* __restrict__ out,
                          int n, float s)
{
    int i = blockIdx.x * 256 + threadIdx.x;
    if (i < n) out[i] = in[i] * s;
}
__global__ void concat_bias(const float* __restrict__ bk,
                            const float* __restrict__ bv,
                            float* __restrict__ out)
{
    int t = threadIdx.x;
    out[t] = (t < 128) ? bk[t] : bv[t - 128];
}

// ---------------------------------------------------------------------------
// HMMA GEMM: C[M,N] = A[M,K](fp16 K-major) @ B[N,K](fp16 K-major)^T + bias
// 128x128 CTA tile, BK=32, 3-stage cp.async pipeline, 256 threads (8 warps),
// warp tile 64x32. OutT = float or __half.
// ---------------------------------------------------------------------------
#define PAD 40
#define STG (128 * PAD)
#define AOFF(st) ((st) * STG * 2)
#define BOFF(st) (3 * STG * 2 + (st) * STG * 2)
#define GEMM_SMEM (6 * STG * 2)

template<typename OutT>
__global__ void __launch_bounds__(256)
gemm_hmma(const __half* __restrict__ A, const __half* __restrict__ B,
          const float* __restrict__ bias, OutT* __restrict__ C,
          int M, int N, int K)
{
    extern __shared__ __half sh[];
    const uint32_t smb = smem_u32(sh);

    const int tid  = threadIdx.x;
    const int wid  = tid >> 5;
    const int lane = tid & 31;
    const int bm = blockIdx.y * 128;
    const int bn = blockIdx.x * 128;
    const int m0 = (wid >> 2) * 64;
    const int n0 = (wid & 3) * 32;

    const int lrow = tid >> 2;
    const int lch  = tid & 3;

    float c[4][4][4];
    #pragma unroll
    for (int mt = 0; mt < 4; mt++)
        #pragma unroll
        for (int nt = 0; nt < 4; nt++)
            #pragma unroll
            for (int r = 0; r < 4; r++) c[mt][nt][r] = 0.f;

    const __half* Ab = A + (size_t)bm * K;
    const __half* Bb = B + (size_t)bn * K;
    const int nk = K / 32;

    auto load_stage = [&](int st, int k0) {
        #pragma unroll
        for (int r = 0; r < 2; r++) {
            const int row = lrow + r * 64;
            const uint32_t so = (uint32_t)(row * PAD + lch * 8) * 2;
            CP16(smb + AOFF(st) + so, Ab + (size_t)row * K + k0 + lch * 8);
            CP16(smb + BOFF(st) + so, Bb + (size_t)row * K + k0 + lch * 8);
        }
    };

    load_stage(0, 0);  CP_COMMIT();
    load_stage(1, 32); CP_COMMIT();

    const int a_r = lane & 15, a_c = (lane >> 4) * 8;
    const int b_r = lane & 7,  b_c = ((lane >> 3) & 1) * 8;

    for (int i = 0; i < nk; i++) {
        CP_WAIT1();
        __syncthreads();
        if (i + 2 < nk) load_stage((i + 2) % 3, (i + 2) * 32);
        CP_COMMIT();

        const int st = i % 3;
        #pragma unroll
        for (int ks = 0; ks < 2; ks++) {
            uint32_t a[4][4], b[4][2];
            #pragma unroll
            for (int mt = 0; mt < 4; mt++) {
                const uint32_t addr = smb + AOFF(st) +
                    (uint32_t)((m0 + mt * 16 + a_r) * PAD + ks * 16 + a_c) * 2;
                LDSM_X4(a[mt][0], a[mt][1], a[mt][2], a[mt][3], addr);
            }
            #pragma unroll
            for (int nt = 0; nt < 4; nt++) {
                const uint32_t addr = smb + BOFF(st) +
                    (uint32_t)((n0 + nt * 8 + b_r) * PAD + ks * 16 + b_c) * 2;
                LDSM_X2(b[nt][0], b[nt][1], addr);
            }
            #pragma unroll
            for (int mt = 0; mt < 4; mt++)
                #pragma unroll
                for (int nt = 0; nt < 4; nt++)
                    MMA16816(c[mt][nt][0], c[mt][nt][1], c[mt][nt][2], c[mt][nt][3],
                             a[mt][0], a[mt][1], a[mt][2], a[mt][3],
                             b[nt][0], b[nt][1]);
        }
        __syncthreads();
    }

    const int tr  = lane >> 2;
    const int tc2 = (lane & 3) * 2;
    #pragma unroll
    for (int mt = 0; mt < 4; mt++) {
        const int r0 = bm + m0 + mt * 16 + tr;
        #pragma unroll
        for (int nt = 0; nt < 4; nt++) {
            const int cc = bn + n0 + nt * 8 + tc2;
            const float bx = bias[cc], by = bias[cc + 1];
            if constexpr (sizeof(OutT) == 4) {
                float2 o0 = make_float2(c[mt][nt][0] + bx, c[mt][nt][1] + by);
                float2 o1 = make_float2(c[mt][nt][2] + bx, c[mt][nt][3] + by);
                *(float2*)&C[(size_t)r0 * N + cc]       = o0;
                *(float2*)&C[(size_t)(r0 + 8) * N + cc] = o1;
            } else {
                *(__half2*)&C[(size_t)r0 * N + cc] =
                    __floats2half2_rn(c[mt][nt][0] + bx, c[mt][nt][1] + by);
                *(__half2*)&C[(size_t)(r0 + 8) * N + cc] =
                    __floats2half2_rn(c[mt][nt][2] + bx, c[mt][nt][3] + by);
            }
        }
    }
}

// ---------------------------------------------------------------------------
// HMMA MQA flash attention. CTA = 64 q-rows x 1 head. 128 threads / 4 warps;
// each warp owns 16 rows. Online softmax fully in registers (FA2 layout).
// KV tiles of 64, double-buffered via cp.async from fused K|V buffer.
// SMEM halves: Q[64][136] @0, K0 @8704, V0 @17408, K1 @26112, V1 @34816.
// ---------------------------------------------------------------------------
#define ATT_SMEM (43520 * 2)

__global__ void __launch_bounds__(128)
mqa_attn_h(const __half* __restrict__ qh, const __half* __restrict__ kvh,
           __half* __restrict__ ao)
{
    extern __shared__ __half sh[];
    const uint32_t smb = smem_u32(sh);

    const int tid = threadIdx.x, wid = tid >> 5, lane = tid & 31;
    const int qt = gridDim.x - 1 - blockIdx.x;     // heavy tiles first
    const int h = blockIdx.y, b = blockIdx.z;
    const int q0 = qt * 64;
    const int ntk = qt + 1;
    const int gid = lane >> 2, tig = lane & 3;
    const int m0w = wid * 16;

    // ---- Q tile load (cp.async) ----
    {
        const __half* qg = qh + (size_t)(b * SB + q0) * NE + h * HD;
        #pragma unroll
        for (int i = 0; i < 8; i++) {
            const int c = i * 128 + tid;
            const int row = c >> 4, ch = c & 15;
            CP16(smb + (uint32_t)(row * 136 + ch * 8) * 2,
                 qg + (size_t)row * NE + ch * 8);
        }
    }
    CP_COMMIT();

    auto load_kv = [&](int jt, int buf) {
        const __half* g = kvh + (size_t)(b * SB + jt * 64) * 256;
        const uint32_t kb = 8704u + (uint32_t)buf * 17408u;
        #pragma unroll
        for (int i = 0; i < 16; i++) {
            const int c = i * 128 + tid;
            const int row = c >> 5, ch = c & 31;
            const uint32_t off = kb + ((ch & 16) ? 8704u : 0u)
                               + (uint32_t)(row * 136 + (ch & 15) * 8);
            CP16(smb + off * 2, g + (size_t)row * 256 + ch * 8);
        }
    };
    load_kv(0, 0);
    CP_COMMIT();
    CP_WAIT0();
    __syncthreads();

    // ---- preload Q fragments (held in registers for whole kernel) ----
    uint32_t qa[8][4];
    {
        const int a_r = lane & 15, a_c = (lane >> 4) * 8;
        #pragma unroll
        for (int kt = 0; kt < 8; kt++) {
            const uint32_t addr = smb +
                (uint32_t)((m0w + a_r) * 136 + kt * 16 + a_c) * 2;
            LDSM_X4(qa[kt][0], qa[kt][1], qa[kt][2], qa[kt][3], addr);
        }
    }

    float co[16][4];
    #pragma unroll
    for (int n = 0; n < 16; n++)
        #pragma unroll
        for (int r = 0; r < 4; r++) co[n][r] = 0.f;
    float m0 = -1e30f, m1 = -1e30f, l0 = 0.f, l1 = 0.f;

    for (int jt = 0; jt < ntk; jt++) {
        if (jt > 0) { CP_WAIT0(); __syncthreads(); }
        if (jt + 1 < ntk) { load_kv(jt + 1, (jt + 1) & 1); CP_COMMIT(); }

        const int buf = jt & 1;
        const uint32_t kbB = smb + (8704u + (uint32_t)buf * 17408u) * 2u;
        const uint32_t vbB = kbB + 8704u * 2u;

        // ---- S = Q K^T ----
        float s[8][4];
        #pragma unroll
        for (int n = 0; n < 8; n++)
            #pragma unroll
            for (int r = 0; r < 4; r++) s[n][r] = 0.f;

        #pragma unroll
        for (int kt = 0; kt < 8; kt++) {
            #pragma unroll
            for (int np = 0; np < 4; np++) {
                uint32_t b0, b1, b2, b3;
                const uint32_t addr = kbB + (uint32_t)(
                    (np * 16 + ((lane >> 4) << 3) + (lane & 7)) * 136
                    + kt * 16 + ((lane >> 3) & 1) * 8) * 2;
                LDSM_X4(b0, b1, b2, b3, addr);
                MMA16816(s[2*np][0], s[2*np][1], s[2*np][2], s[2*np][3],
                         qa[kt][0], qa[kt][1], qa[kt][2], qa[kt][3], b0, b1);
                MMA16816(s[2*np+1][0], s[2*np+1][1], s[2*np+1][2], s[2*np+1][3],
                         qa[kt][0], qa[kt][1], qa[kt][2], qa[kt][3], b2, b3);
            }
        }

        // ---- causal mask (diagonal tile only) ----
        if (jt == ntk - 1) {
            const int r0 = m0w + gid, r1 = r0 + 8;
            #pragma unroll
            for (int nt = 0; nt < 8; nt++) {
                const int c0 = nt * 8 + tig * 2, c1 = c0 + 1;
                if (c0 > r0) s[nt][0] = -1e30f;
                if (c1 > r0) s[nt][1] = -1e30f;
                if (c0 > r1) s[nt][2] = -1e30f;
                if (c1 > r1) s[nt][3] = -1e30f;
            }
        }

        // ---- online softmax (register-resident) ----
        float mx0 = -1e30f, mx1 = -1e30f;
        #pragma unroll
        for (int nt = 0; nt < 8; nt++) {
            mx0 = fmaxf(mx0, fmaxf(s[nt][0], s[nt][1]));
            mx1 = fmaxf(mx1, fmaxf(s[nt][2], s[nt][3]));
        }
        mx0 = fmaxf(mx0, __shfl_xor_sync(0xffffffffu, mx0, 1));
        mx0 = fmaxf(mx0, __shfl_xor_sync(0xffffffffu, mx0, 2));
        mx1 = fmaxf(mx1, __shfl_xor_sync(0xffffffffu, mx1, 1));
        mx1 = fmaxf(mx1, __shfl_xor_sync(0xffffffffu, mx1, 2));

        const float mn0 = fmaxf(m0, mx0), mn1 = fmaxf(m1, mx1);
        const float al0 = __expf(m0 - mn0), al1 = __expf(m1 - mn1);
        float ls0 = 0.f, ls1 = 0.f;
        #pragma unroll
        for (int nt = 0; nt < 8; nt++) {
            s[nt][0] = __expf(s[nt][0] - mn0);
            s[nt][1] = __expf(s[nt][1] - mn0);
            s[nt][2] = __expf(s[nt][2] - mn1);
            s[nt][3] = __expf(s[nt][3] - mn1);
            ls0 += s[nt][0] + s[nt][1];
            ls1 += s[nt][2] + s[nt][3];
        }
        ls0 += __shfl_xor_sync(0xffffffffu, ls0, 1);
        ls0 += __shfl_xor_sync(0xffffffffu, ls0, 2);
        ls1 += __shfl_xor_sync(0xffffffffu, ls1, 1);
        ls1 += __shfl_xor_sync(0xffffffffu, ls1, 2);
        l0 = l0 * al0 + ls0;  l1 = l1 * al1 + ls1;
        m0 = mn0;  m1 = mn1;

        #pragma unroll
        for (int nt = 0; nt < 16; nt++) {
            co[nt][0] *= al0; co[nt][1] *= al0;
            co[nt][2] *= al1; co[nt][3] *= al1;
        }

        // ---- P fragments (in-register repack: S accum -> A operand) ----
        uint32_t pa[4][4];
        #pragma unroll
        for (int t = 0; t < 4; t++) {
            pa[t][0] = pack_h2(s[2*t][0],   s[2*t][1]);
            pa[t][1] = pack_h2(s[2*t][2],   s[2*t][3]);
            pa[t][2] = pack_h2(s[2*t+1][0], s[2*t+1][1]);
            pa[t][3] = pack_h2(s[2*t+1][2], s[2*t+1][3]);
        }

        // ---- O += P V ----
        #pragma unroll
        for (int t = 0; t < 4; t++) {
            #pragma unroll
            for (int dp = 0; dp < 8; dp++) {
                uint32_t b0, b1, b2, b3;
                const uint32_t addr = vbB + (uint32_t)(
                    (t * 16 + ((lane >> 3) & 1) * 8 + (lane & 7)) * 136
                    + dp * 16 + (lane >> 4) * 8) * 2;
                LDSM_X4T(b0, b1, b2, b3, addr);
                MMA16816(co[2*dp][0], co[2*dp][1], co[2*dp][2], co[2*dp][3],
                         pa[t][0], pa[t][1], pa[t][2], pa[t][3], b0, b1);
                MMA16816(co[2*dp+1][0], co[2*dp+1][1], co[2*dp+1][2], co[2*dp+1][3],
                         pa[t][0], pa[t][1], pa[t][2], pa[t][3], b2, b3);
            }
        }
    }

    // ---- finalize ----
    const float inv0 = 1.f / l0, inv1 = 1.f / l1;
    const int r0 = q0 + m0w + gid, r1 = r0 + 8;
    __half* o0 = ao + (size_t)(b * SB + r0) * NE + h * HD;
    __half* o1 = ao + (size_t)(b * SB + r1) * NE + h * HD;
    #pragma unroll
    for (int nt = 0; nt < 16; nt++) {
        const int cc = nt * 8 + tig * 2;
        *(__half2*)(o0 + cc) = __floats2half2_rn(co[nt][0] * inv0, co[nt][1] * inv0);
        *(__half2*)(o1 + cc) = __floats2half2_rn(co[nt][2] * inv1, co[nt][3] * inv1);
    }
}

// ---------------------------------------------------------------------------
extern "C" void kernel_launch(void* const* d_in, const int* in_sizes, int n_in,
                              void* d_out, int out_size)
{
    const float* x  = (const float*)d_in[0];
    const float* Wq = (const float*)d_in[1];
    const float* bq = (const float*)d_in[2];
    const float* Wk = (const float*)d_in[3];
    const float* bk = (const float*)d_in[4];
    const float* Wv = (const float*)d_in[5];
    const float* bv = (const float*)d_in[6];
    const float* Wo = (const float*)d_in[7];
    const float* bo = (const float*)d_in[8];
    float* out = (float*)d_out;

    __half *xh, *qhp, *kvh, *aoh, *wqh, *wkvh, *woh;
    float *bqs, *bkv;
    cudaGetSymbolAddress((void**)&xh,   g_xh);
    cudaGetSymbolAddress((void**)&qhp,  g_qh);
    cudaGetSymbolAddress((void**)&kvh,  g_kvh);
    cudaGetSymbolAddress((void**)&aoh,  g_aoh);
    cudaGetSymbolAddress((void**)&wqh,  g_wqh);
    cudaGetSymbolAddress((void**)&wkvh, g_wkvh);
    cudaGetSymbolAddress((void**)&woh,  g_woh);
    cudaGetSymbolAddress((void**)&bqs,  g_bqs);
    cudaGetSymbolAddress((void**)&bkv,  g_bkv);

    cudaFuncSetAttribute(gemm_hmma<float>,  cudaFuncAttributeMaxDynamicSharedMemorySize, GEMM_SMEM);
    cudaFuncSetAttribute(gemm_hmma<__half>, cudaFuncAttributeMaxDynamicSharedMemorySize, GEMM_SMEM);
    cudaFuncSetAttribute(mqa_attn_h, cudaFuncAttributeMaxDynamicSharedMemorySize, ATT_SMEM);

    const float scale = 0.08838834764831845f;   // 1/sqrt(128)
    dim3 blk(256);

    // conversions (scale folded into Wq/bq)
    f32_to_f16  <<<(MT * NE) / 1024, blk>>>(x,  xh,  MT * NE);
    f32_to_f16_s<<<(NE * NE) / 1024, blk>>>(Wq, wqh, NE * NE, scale);
    f32_to_f16  <<<(HD * NE) / 1024, blk>>>(Wk, wkvh,           HD * NE);
    f32_to_f16  <<<(HD * NE) / 1024, blk>>>(Wv, wkvh + HD * NE, HD * NE);
    f32_to_f16  <<<(NE * NE) / 1024, blk>>>(Wo, woh, NE * NE);
    scale_f32<<<NE / 256, blk>>>(bq, bqs, NE, scale);
    concat_bias<<<1, 256>>>(bk, bv, bkv);

    // projections (fp16 outputs)
    gemm_hmma<__half><<<dim3(NE / 128, MT / 128), blk, GEMM_SMEM>>>(xh, wqh,  bqs, qhp, MT, NE,  NE);
    gemm_hmma<__half><<<dim3(256 / 128, MT / 128), blk, GEMM_SMEM>>>(xh, wkvh, bkv, kvh, MT, 256, NE);

    // HMMA flash attention
    mqa_attn_h<<<dim3(SB / 64, NH, NB), dim3(128), ATT_SMEM>>>(qhp, kvh, aoh);

    // output projection (fp32 output)
    gemm_hmma<float><<<dim3(NE / 128, MT / 128), blk, GEMM_SMEM>>>(aoh, woh, bo, out, MT, NE, NE);
}